// round 2
// baseline (speedup 1.0000x reference)
#include <cuda_runtime.h>
#include <cuda_bf16.h>
#include <cstdint>

#define N_NODES 100000
#define E_EDGES 600000
#define D 128
#define ALPHA 0.5f

// ---------------- scratch (static device globals; no allocations) ----------
__device__ float g_y[(size_t)N_NODES * 256];   // [N][256]: [:,0:128]=(1-a)xWsrc^T, [:,128:256]=a xWdst^T
__device__ float g_Wc[256 * D];                // combined, pre-scaled weights [256][128]
__device__ float g_iso[N_NODES];               // deg_out^-1/2
__device__ float g_isi[N_NODES];               // deg_in^-1/2

// ---------------- kernels ---------------------------------------------------

__global__ void zero_deg_kernel() {
    int i = blockIdx.x * blockDim.x + threadIdx.x;
    if (i < N_NODES) { g_iso[i] = 0.f; g_isi[i] = 0.f; }
}

// count degrees into g_iso/g_isi (reused as raw counters, converted in place)
__global__ void degree_kernel(const int* __restrict__ ei) {
    int e = blockIdx.x * blockDim.x + threadIdx.x;
    if (e >= E_EDGES) return;
    int r = ei[e];
    int c = ei[E_EDGES + e];
    atomicAdd(&g_iso[r], 1.f);
    atomicAdd(&g_isi[c], 1.f);
}

__global__ void inv_sqrt_kernel() {
    int i = blockIdx.x * blockDim.x + threadIdx.x;
    if (i >= N_NODES) return;
    float d = g_iso[i];
    g_iso[i] = (d > 0.f) ? rsqrtf(d) : 0.f;
    d = g_isi[i];
    g_isi[i] = (d > 0.f) ? rsqrtf(d) : 0.f;
}

// build combined pre-scaled weight matrix [256][128]
__global__ void prep_wc_kernel(const float* __restrict__ Wsrc,
                               const float* __restrict__ Wdst) {
    int i = blockIdx.x * blockDim.x + threadIdx.x;  // 0 .. 256*128-1
    if (i >= 256 * D) return;
    int f = i >> 7;           // output feature 0..255
    int k = i & 127;
    if (f < D)
        g_Wc[i] = (1.0f - ALPHA) * Wsrc[f * D + k];
    else
        g_Wc[i] = ALPHA * Wdst[(f - D) * D + k];
}

// y[m][n] = sum_k x[m][k] * Wc[n][k]   (M=100000, N=256, K=128)
// 64x64 output tile per 256-thread CTA; K processed in 2 chunks of 64 so the
// [k][m]-layout (pad 65) tiles fit in 33.3 KB STATIC shared memory.
#define TM 64
#define TN 64
#define KC 64
__global__ void gemm_kernel(const float* __restrict__ x) {
    __shared__ float As[KC * 65];
    __shared__ float Bs[KC * 65];
    const int m0 = blockIdx.x * TM;
    const int n0 = blockIdx.y * TN;
    const int tid = threadIdx.x;

    const int tx = tid & 15;   // col group
    const int ty = tid >> 4;   // row group
    float acc[4][4];
#pragma unroll
    for (int i = 0; i < 4; i++)
#pragma unroll
        for (int j = 0; j < 4; j++) acc[i][j] = 0.f;

    for (int kc = 0; kc < D; kc += KC) {
        // load A tile: rows m0..m0+63, k in [kc, kc+64)
#pragma unroll
        for (int it = 0; it < 16; it++) {
            int idx = it * 256 + tid;
            int k = idx & 63, r = idx >> 6;
            int gm = m0 + r;
            As[k * 65 + r] = (gm < N_NODES) ? x[(size_t)gm * D + kc + k] : 0.f;
        }
        // load B tile: Wc rows n0..n0+63, k in [kc, kc+64)
#pragma unroll
        for (int it = 0; it < 16; it++) {
            int idx = it * 256 + tid;
            int k = idx & 63, c = idx >> 6;
            Bs[k * 65 + c] = g_Wc[(n0 + c) * D + kc + k];
        }
        __syncthreads();

#pragma unroll 8
        for (int k = 0; k < KC; k++) {
            float a[4], b[4];
#pragma unroll
            for (int i = 0; i < 4; i++) a[i] = As[k * 65 + ty + 16 * i];
#pragma unroll
            for (int j = 0; j < 4; j++) b[j] = Bs[k * 65 + tx + 16 * j];
#pragma unroll
            for (int i = 0; i < 4; i++)
#pragma unroll
                for (int j = 0; j < 4; j++) acc[i][j] += a[i] * b[j];
        }
        __syncthreads();
    }

#pragma unroll
    for (int i = 0; i < 4; i++) {
        int gm = m0 + ty + 16 * i;
        if (gm >= N_NODES) continue;
#pragma unroll
        for (int j = 0; j < 4; j++) {
            g_y[(size_t)gm * 256 + n0 + tx + 16 * j] = acc[i][j];
        }
    }
}

// out init with combined bias (bias is zero in this dataset, but stay general)
__global__ void init_out_kernel(float* __restrict__ out,
                                const float* __restrict__ bsrc,
                                const float* __restrict__ bdst) {
    int i = blockIdx.x * blockDim.x + threadIdx.x;  // N*D elements
    if (i >= N_NODES * D) return;
    int f = i & 127;
    out[i] = (1.0f - ALPHA) * bsrc[f] + ALPHA * bdst[f];
}

// warp per edge: out[row] += w * y[col][0:128];  out[col] += w * y[row][128:256]
__global__ void scatter_kernel(const int* __restrict__ ei,
                               float* __restrict__ out) {
    int gw = (blockIdx.x * blockDim.x + threadIdx.x) >> 5;
    if (gw >= E_EDGES) return;
    const int lane = threadIdx.x & 31;

    const int r = __ldg(&ei[gw]);
    const int c = __ldg(&ei[E_EDGES + gw]);
    const float w = __ldg(&g_iso[r]) * __ldg(&g_isi[c]);

    const float4* ys = reinterpret_cast<const float4*>(&g_y[(size_t)c * 256]);
    const float4* yd = reinterpret_cast<const float4*>(&g_y[(size_t)r * 256 + 128]);
    float4 vs = __ldg(&ys[lane]);
    float4 vd = __ldg(&yd[lane]);
    vs.x *= w; vs.y *= w; vs.z *= w; vs.w *= w;
    vd.x *= w; vd.y *= w; vd.z *= w; vd.w *= w;

    // documented sm_90+ vector atomics -> REDG.128 when result is unused
    atomicAdd(reinterpret_cast<float4*>(out + (size_t)r * D) + lane, vs);
    atomicAdd(reinterpret_cast<float4*>(out + (size_t)c * D) + lane, vd);
}

// ---------------- launch -----------------------------------------------------

extern "C" void kernel_launch(void* const* d_in, const int* in_sizes, int n_in,
                              void* d_out, int out_size) {
    const float* x    = (const float*)d_in[0];
    const int*   ei   = (const int*)d_in[1];     // int32! (jax x64 disabled)
    const float* Wsrc = (const float*)d_in[2];
    const float* bsrc = (const float*)d_in[3];
    const float* Wdst = (const float*)d_in[4];
    const float* bdst = (const float*)d_in[5];
    float*       out  = (float*)d_out;

    zero_deg_kernel<<<(N_NODES + 255) / 256, 256>>>();
    degree_kernel<<<(E_EDGES + 255) / 256, 256>>>(ei);
    inv_sqrt_kernel<<<(N_NODES + 255) / 256, 256>>>();
    prep_wc_kernel<<<(256 * D + 255) / 256, 256>>>(Wsrc, Wdst);

    dim3 gemm_grid((N_NODES + TM - 1) / TM, 256 / TN);  // 1563 x 4
    gemm_kernel<<<gemm_grid, 256>>>(x);

    init_out_kernel<<<(N_NODES * D + 255) / 256, 256>>>(out, bsrc, bdst);

    // 8 warps per 256-thread block, warp per edge
    scatter_kernel<<<(E_EDGES + 7) / 8, 256>>>(ei, out);
}

// round 4
// speedup vs baseline: 1.0626x; 1.0626x over previous
#include <cuda_runtime.h>
#include <cuda_bf16.h>
#include <cstdint>

#define N_NODES 100000
#define E_EDGES 600000
#define D 128
#define ALPHA 0.5f

// ---------------- scratch (static device globals; no allocations) ----------
__device__ float g_y[(size_t)N_NODES * 256];   // [N][256]: [:,0:128]=(1-a)xWsrc^T, [:,128:256]=a xWdst^T
__device__ float g_Wc[256 * D];                // combined, pre-scaled weights [256][128]
__device__ float g_iso[N_NODES];               // deg_out^-1/2
__device__ float g_isi[N_NODES];               // deg_in^-1/2

// ---------------- f32x2 helpers (FFMA2: 2x fp32 FMA per issue slot) --------
__device__ __forceinline__ unsigned long long pk2(float lo, float hi) {
    unsigned long long r;
    asm("mov.b64 %0, {%1, %2};" : "=l"(r) : "f"(lo), "f"(hi));
    return r;
}
__device__ __forceinline__ void upk2(unsigned long long v, float& lo, float& hi) {
    asm("mov.b64 {%0, %1}, %2;" : "=f"(lo), "=f"(hi) : "l"(v));
}
__device__ __forceinline__ void fma2(unsigned long long& acc,
                                     unsigned long long a, unsigned long long b) {
    asm("fma.rn.f32x2 %0, %1, %2, %0;" : "+l"(acc) : "l"(a), "l"(b));
}

// ---------------- kernels ---------------------------------------------------

// fused init: zero degree counters, build combined pre-scaled weights, and
// write the combined bias into out (bias zero in dataset, kept general)
__global__ void init_all_kernel(float* __restrict__ out,
                                const float* __restrict__ Wsrc,
                                const float* __restrict__ Wdst,
                                const float* __restrict__ bsrc,
                                const float* __restrict__ bdst) {
    int i = blockIdx.x * blockDim.x + threadIdx.x;
    if (i >= N_NODES * D) return;
    if (i < N_NODES) { g_iso[i] = 0.f; g_isi[i] = 0.f; }
    if (i < 256 * D) {
        int f = i >> 7, k = i & 127;
        g_Wc[i] = (f < D) ? (1.0f - ALPHA) * Wsrc[f * D + k]
                          : ALPHA * Wdst[(f - D) * D + k];
    }
    int f = i & 127;
    out[i] = (1.0f - ALPHA) * bsrc[f] + ALPHA * bdst[f];
}

__global__ void degree_kernel(const int* __restrict__ ei) {
    int e = blockIdx.x * blockDim.x + threadIdx.x;
    if (e >= E_EDGES) return;
    atomicAdd(&g_iso[ei[e]], 1.f);
    atomicAdd(&g_isi[ei[E_EDGES + e]], 1.f);
}

__global__ void inv_sqrt_kernel() {
    int i = blockIdx.x * blockDim.x + threadIdx.x;
    if (i >= N_NODES) return;
    float d = g_iso[i];
    g_iso[i] = (d > 0.f) ? rsqrtf(d) : 0.f;
    d = g_isi[i];
    g_isi[i] = (d > 0.f) ? rsqrtf(d) : 0.f;
}

// y[m][n] = sum_k x[m][k] * Wc[n][k]   (M=100000, N=256, K=128)
// 64x64 tile / 256 threads; thread owns 4 consecutive rows x 4 consecutive
// cols so LDS.128 feeds the packed-f32x2 inner loop. Accumulators are f32x2
// pairs along n (b-pairs free from the float4; a needs broadcast packs).
#define TM 64
#define TN 64
#define KC 64
#define PAD 68   // words per k-row (64 + 4), keeps 16B alignment, rotates banks
__global__ void gemm_kernel(const float* __restrict__ x) {
    __shared__ float As[KC * PAD];   // [k][m] 17.4 KB
    __shared__ float Bs[KC * PAD];   // [k][n] 17.4 KB
    const int m0 = blockIdx.x * TM;
    const int n0 = blockIdx.y * TN;
    const int tid = threadIdx.x;
    const int tx = tid & 15;    // col group: cols n0 + 4*tx .. +3
    const int ty = tid >> 4;    // row group: rows m0 + 4*ty .. +3

    unsigned long long acc[4][2];
#pragma unroll
    for (int i = 0; i < 4; i++) { acc[i][0] = 0ull; acc[i][1] = 0ull; }

    for (int kc = 0; kc < D; kc += KC) {
#pragma unroll
        for (int it = 0; it < 16; it++) {
            int idx = it * 256 + tid;
            int k = idx & 63, r = idx >> 6;
            int gm = m0 + r;
            As[k * PAD + r] = (gm < N_NODES) ? x[(size_t)gm * D + kc + k] : 0.f;
        }
#pragma unroll
        for (int it = 0; it < 16; it++) {
            int idx = it * 256 + tid;
            int k = idx & 63, c = idx >> 6;
            Bs[k * PAD + c] = g_Wc[(n0 + c) * D + kc + k];
        }
        __syncthreads();

#pragma unroll 8
        for (int k = 0; k < KC; k++) {
            float4 av = *reinterpret_cast<const float4*>(&As[k * PAD + 4 * ty]);
            float4 bv = *reinterpret_cast<const float4*>(&Bs[k * PAD + 4 * tx]);
            unsigned long long bp0 = pk2(bv.x, bv.y);
            unsigned long long bp1 = pk2(bv.z, bv.w);
            unsigned long long a0 = pk2(av.x, av.x);
            unsigned long long a1 = pk2(av.y, av.y);
            unsigned long long a2 = pk2(av.z, av.z);
            unsigned long long a3 = pk2(av.w, av.w);
            fma2(acc[0][0], a0, bp0); fma2(acc[0][1], a0, bp1);
            fma2(acc[1][0], a1, bp0); fma2(acc[1][1], a1, bp1);
            fma2(acc[2][0], a2, bp0); fma2(acc[2][1], a2, bp1);
            fma2(acc[3][0], a3, bp0); fma2(acc[3][1], a3, bp1);
        }
        __syncthreads();
    }

#pragma unroll
    for (int i = 0; i < 4; i++) {
        int gm = m0 + 4 * ty + i;
        if (gm >= N_NODES) continue;
        float4 o;
        upk2(acc[i][0], o.x, o.y);
        upk2(acc[i][1], o.z, o.w);
        *reinterpret_cast<float4*>(&g_y[(size_t)gm * 256 + n0 + 4 * tx]) = o;
    }
}

// warp per edge: out[row] += w * y[col][0:128];  out[col] += w * y[row][128:256]
__global__ void scatter_kernel(const int* __restrict__ ei,
                               float* __restrict__ out) {
    int gw = (blockIdx.x * blockDim.x + threadIdx.x) >> 5;
    if (gw >= E_EDGES) return;
    const int lane = threadIdx.x & 31;

    const int r = __ldg(&ei[gw]);
    const int c = __ldg(&ei[E_EDGES + gw]);
    const float w = __ldg(&g_iso[r]) * __ldg(&g_isi[c]);

    const float4* ys = reinterpret_cast<const float4*>(&g_y[(size_t)c * 256]);
    const float4* yd = reinterpret_cast<const float4*>(&g_y[(size_t)r * 256 + 128]);
    float4 vs = __ldg(&ys[lane]);
    float4 vd = __ldg(&yd[lane]);
    vs.x *= w; vs.y *= w; vs.z *= w; vs.w *= w;
    vd.x *= w; vd.y *= w; vd.z *= w; vd.w *= w;

    atomicAdd(reinterpret_cast<float4*>(out + (size_t)r * D) + lane, vs);
    atomicAdd(reinterpret_cast<float4*>(out + (size_t)c * D) + lane, vd);
}

// ---------------- launch -----------------------------------------------------

extern "C" void kernel_launch(void* const* d_in, const int* in_sizes, int n_in,
                              void* d_out, int out_size) {
    const float* x    = (const float*)d_in[0];
    const int*   ei   = (const int*)d_in[1];     // int32 (jax x64 disabled)
    const float* Wsrc = (const float*)d_in[2];
    const float* bsrc = (const float*)d_in[3];
    const float* Wdst = (const float*)d_in[4];
    const float* bdst = (const float*)d_in[5];
    float*       out  = (float*)d_out;

    init_all_kernel<<<(N_NODES * D + 255) / 256, 256>>>(out, Wsrc, Wdst, bsrc, bdst);
    degree_kernel<<<(E_EDGES + 255) / 256, 256>>>(ei);
    inv_sqrt_kernel<<<(N_NODES + 255) / 256, 256>>>();

    dim3 gemm_grid((N_NODES + TM - 1) / TM, 256 / TN);  // 1563 x 4
    gemm_kernel<<<gemm_grid, 256>>>(x);

    scatter_kernel<<<(E_EDGES + 7) / 8, 256>>>(ei, out);
}

// round 7
// speedup vs baseline: 1.3548x; 1.2749x over previous
#include <cuda_runtime.h>
#include <cuda_bf16.h>
#include <cstdint>

#define N_NODES 100000
#define E_EDGES 600000
#define D 128
#define ALPHA 0.5f

// ---------------- scratch (static device globals; no allocations) ----------
__device__ float g_y[(size_t)N_NODES * 256];   // [N][256]
__device__ float g_Wc[256 * D];                // combined, pre-scaled weights [256][128]
__device__ float g_iso[N_NODES];               // deg_out^-1/2
__device__ float g_isi[N_NODES];               // deg_in^-1/2

// ---------------- f32x2 helpers (FFMA2: 2x fp32 FMA per issue slot) --------
__device__ __forceinline__ unsigned long long pk2(float lo, float hi) {
    unsigned long long r;
    asm("mov.b64 %0, {%1, %2};" : "=l"(r) : "f"(lo), "f"(hi));
    return r;
}
__device__ __forceinline__ void upk2(unsigned long long v, float& lo, float& hi) {
    asm("mov.b64 {%0, %1}, %2;" : "=f"(lo), "=f"(hi) : "l"(v));
}
__device__ __forceinline__ void fma2(unsigned long long& acc,
                                     unsigned long long a, unsigned long long b) {
    asm("fma.rn.f32x2 %0, %1, %2, %0;" : "+l"(acc) : "l"(a), "l"(b));
}

// ---------------- kernels ---------------------------------------------------

__global__ void init_all_kernel(float* __restrict__ out,
                                const float* __restrict__ Wsrc,
                                const float* __restrict__ Wdst,
                                const float* __restrict__ bsrc,
                                const float* __restrict__ bdst) {
    int i = blockIdx.x * blockDim.x + threadIdx.x;
    if (i >= N_NODES * D) return;
    if (i < N_NODES) { g_iso[i] = 0.f; g_isi[i] = 0.f; }
    if (i < 256 * D) {
        int f = i >> 7, k = i & 127;
        g_Wc[i] = (f < D) ? (1.0f - ALPHA) * Wsrc[f * D + k]
                          : ALPHA * Wdst[(f - D) * D + k];
    }
    int f = i & 127;
    out[i] = (1.0f - ALPHA) * bsrc[f] + ALPHA * bdst[f];
}

__global__ void degree_kernel(const int* __restrict__ ei) {
    int e = blockIdx.x * blockDim.x + threadIdx.x;
    if (e >= E_EDGES) return;
    atomicAdd(&g_iso[ei[e]], 1.f);
    atomicAdd(&g_isi[ei[E_EDGES + e]], 1.f);
}

__global__ void inv_sqrt_kernel() {
    int i = blockIdx.x * blockDim.x + threadIdx.x;
    if (i >= N_NODES) return;
    float d = g_iso[i];
    g_iso[i] = (d > 0.f) ? rsqrtf(d) : 0.f;
    d = g_isi[i];
    g_isi[i] = (d > 0.f) ? rsqrtf(d) : 0.f;
}

// y[m][n] = sum_k x[m][k] * Wc[n][k]   (M=100000, N=256, K=128)
// 128x128 CTA tile, 256 threads, 8x8 per-thread register tile.
// Per k-step: 4 LDS.128 feed 32 FFMA2 (2x the FLOP/LDS of the 4x8 version) --
// shifts the bottleneck from the LDS issue floor (L1=74.7% in R4 profile) to
// the fma pipe. KC=32 so both [k][m]-layout tiles fit static smem (33.8 KB).
#define TM 128
#define TN 128
#define KC 32
#define PAD 132   // words per k-row: 128 + 4 (16B aligned, rotates banks)
__global__ void __launch_bounds__(256, 2) gemm_kernel(const float* __restrict__ x) {
    __shared__ float As[KC * PAD];   // [k][m]
    __shared__ float Bs[KC * PAD];   // [k][n]
    const int m0 = blockIdx.x * TM;
    const int n0 = blockIdx.y * TN;
    const int tid = threadIdx.x;
    const int tx = tid & 15;    // col pair: n0 + 4*tx, n0 + 64 + 4*tx
    const int ty = tid >> 4;    // row pair: m0 + 4*ty, m0 + 64 + 4*ty

    unsigned long long acc[8][4];
#pragma unroll
    for (int i = 0; i < 8; i++)
#pragma unroll
        for (int j = 0; j < 4; j++) acc[i][j] = 0ull;

    for (int kc = 0; kc < D; kc += KC) {
        // A tile: rows m0..m0+127, k in [kc,kc+32). float4 along k.
#pragma unroll
        for (int it = 0; it < 4; it++) {
            int idx = it * 256 + tid;          // 0..1023
            int r = idx >> 3;                  // 0..127
            int kq = idx & 7;                  // float4 index along k
            int gm = m0 + r;
            float4 v = make_float4(0.f, 0.f, 0.f, 0.f);
            if (gm < N_NODES)
                v = *reinterpret_cast<const float4*>(&x[(size_t)gm * D + kc + 4 * kq]);
            As[(4 * kq + 0) * PAD + r] = v.x;
            As[(4 * kq + 1) * PAD + r] = v.y;
            As[(4 * kq + 2) * PAD + r] = v.z;
            As[(4 * kq + 3) * PAD + r] = v.w;
        }
        // B tile: Wc rows n0..n0+127, k in [kc,kc+32)
#pragma unroll
        for (int it = 0; it < 4; it++) {
            int idx = it * 256 + tid;
            int c = idx >> 3;
            int kq = idx & 7;
            float4 v = *reinterpret_cast<const float4*>(&g_Wc[(n0 + c) * D + kc + 4 * kq]);
            Bs[(4 * kq + 0) * PAD + c] = v.x;
            Bs[(4 * kq + 1) * PAD + c] = v.y;
            Bs[(4 * kq + 2) * PAD + c] = v.z;
            Bs[(4 * kq + 3) * PAD + c] = v.w;
        }
        __syncthreads();

#pragma unroll 8
        for (int k = 0; k < KC; k++) {
            float4 a0 = *reinterpret_cast<const float4*>(&As[k * PAD + 4 * ty]);
            float4 a1 = *reinterpret_cast<const float4*>(&As[k * PAD + 64 + 4 * ty]);
            float4 b0 = *reinterpret_cast<const float4*>(&Bs[k * PAD + 4 * tx]);
            float4 b1 = *reinterpret_cast<const float4*>(&Bs[k * PAD + 64 + 4 * tx]);
            unsigned long long bp[4] = { pk2(b0.x, b0.y), pk2(b0.z, b0.w),
                                         pk2(b1.x, b1.y), pk2(b1.z, b1.w) };
            unsigned long long ap[8] = { pk2(a0.x, a0.x), pk2(a0.y, a0.y),
                                         pk2(a0.z, a0.z), pk2(a0.w, a0.w),
                                         pk2(a1.x, a1.x), pk2(a1.y, a1.y),
                                         pk2(a1.z, a1.z), pk2(a1.w, a1.w) };
#pragma unroll
            for (int i = 0; i < 8; i++)
#pragma unroll
                for (int j = 0; j < 4; j++)
                    fma2(acc[i][j], ap[i], bp[j]);
        }
        __syncthreads();
    }

#pragma unroll
    for (int i = 0; i < 8; i++) {
        int gm = m0 + ((i < 4) ? (4 * ty + i) : (64 + 4 * ty + i - 4));
        if (gm >= N_NODES) continue;
        float4 o0, o1;
        upk2(acc[i][0], o0.x, o0.y);
        upk2(acc[i][1], o0.z, o0.w);
        upk2(acc[i][2], o1.x, o1.y);
        upk2(acc[i][3], o1.z, o1.w);
        *reinterpret_cast<float4*>(&g_y[(size_t)gm * 256 + n0 + 4 * tx]) = o0;
        *reinterpret_cast<float4*>(&g_y[(size_t)gm * 256 + n0 + 64 + 4 * tx]) = o1;
    }
}

// warp per edge: out[row] += w * y[col][0:128];  out[col] += w * y[row][128:256]
__global__ void scatter_kernel(const int* __restrict__ ei,
                               float* __restrict__ out) {
    int gw = (blockIdx.x * blockDim.x + threadIdx.x) >> 5;
    if (gw >= E_EDGES) return;
    const int lane = threadIdx.x & 31;

    const int r = __ldg(&ei[gw]);
    const int c = __ldg(&ei[E_EDGES + gw]);
    const float w = __ldg(&g_iso[r]) * __ldg(&g_isi[c]);

    const float4* ys = reinterpret_cast<const float4*>(&g_y[(size_t)c * 256]);
    const float4* yd = reinterpret_cast<const float4*>(&g_y[(size_t)r * 256 + 128]);
    float4 vs = __ldg(&ys[lane]);
    float4 vd = __ldg(&yd[lane]);
    vs.x *= w; vs.y *= w; vs.z *= w; vs.w *= w;
    vd.x *= w; vd.y *= w; vd.z *= w; vd.w *= w;

    atomicAdd(reinterpret_cast<float4*>(out + (size_t)r * D) + lane, vs);
    atomicAdd(reinterpret_cast<float4*>(out + (size_t)c * D) + lane, vd);
}

// ---------------- launch -----------------------------------------------------

extern "C" void kernel_launch(void* const* d_in, const int* in_sizes, int n_in,
                              void* d_out, int out_size) {
    const float* x    = (const float*)d_in[0];
    const int*   ei   = (const int*)d_in[1];     // int32 (jax x64 disabled)
    const float* Wsrc = (const float*)d_in[2];
    const float* bsrc = (const float*)d_in[3];
    const float* Wdst = (const float*)d_in[4];
    const float* bdst = (const float*)d_in[5];
    float*       out  = (float*)d_out;

    init_all_kernel<<<(N_NODES * D + 255) / 256, 256>>>(out, Wsrc, Wdst, bsrc, bdst);
    degree_kernel<<<(E_EDGES + 255) / 256, 256>>>(ei);
    inv_sqrt_kernel<<<(N_NODES + 255) / 256, 256>>>();

    dim3 gemm_grid((N_NODES + TM - 1) / TM, 256 / TN);  // 782 x 2
    gemm_kernel<<<gemm_grid, 256>>>(x);

    scatter_kernel<<<(E_EDGES + 7) / 8, 256>>>(ei, out);
}